// round 12
// baseline (speedup 1.0000x reference)
#include <cuda_runtime.h>
#include <math.h>

#define D_MODEL   3072
#define NUM_E     8
#define TPW       8                       // tokens per warp (one oct)
#define WARPS_PB  16
#define THREADS   (WARPS_PB * 32)         // 512
#define CHUNK_D   128                     // floats of D per stage
#define NCHUNK    (D_MODEL / CHUNK_D)     // 24
#define NSTAGE    2                       // ring slots (ping-pong)
#define GRID      148
#define N_TOKENS  16384
#define NOCTS     (N_TOKENS / TPW)        // 2048 <= 2368 warps: one oct/warp
#define STAGE_BYTES (TPW * CHUNK_D * 4)   // 4096
#define RING_FLOATS_PER_WARP (NSTAGE * TPW * CHUNK_D)   // 2048 floats = 8 KB
#define SMEM_BYTES ((NUM_E * D_MODEL + WARPS_PB * RING_FLOATS_PER_WARP) * 4) // 224 KB

typedef unsigned long long u64;

__device__ __forceinline__ u64 ffma2(u64 a, u64 b, u64 c) {
    u64 d;
    asm("fma.rn.f32x2 %0, %1, %2, %3;" : "=l"(d) : "l"(a), "l"(b), "l"(c));
    return d;
}
__device__ __forceinline__ u64 addf2(u64 a, u64 b) {
    u64 d;
    asm("add.rn.f32x2 %0, %1, %2;" : "=l"(d) : "l"(a), "l"(b));
    return d;
}
__device__ __forceinline__ u64 dup2(float f) {
    u64 r; unsigned u = __float_as_uint(f);
    asm("mov.b64 %0, {%1, %1};" : "=l"(r) : "r"(u));
    return r;
}
__device__ __forceinline__ u64 shflx64(u64 v, int m) {
    unsigned lo = (unsigned)v, hi = (unsigned)(v >> 32);
    lo = __shfl_xor_sync(0xFFFFFFFFu, lo, m);
    hi = __shfl_xor_sync(0xFFFFFFFFu, hi, m);
    return ((u64)hi << 32) | lo;
}
// Paired-transposed W (R10-verified): row d holds e0..e7 (32 B), 16B-granule
// XOR swizzle -> conflict-free LDS.128.
__device__ __forceinline__ unsigned wt_off(int d, int h) {
    unsigned o = (unsigned)d * 32u + (unsigned)h * 16u;
    return o ^ ((((unsigned)d >> 2) & 7u) << 4);
}

__global__ void __launch_bounds__(THREADS, 1)
gating_kernel(const float* __restrict__ x,
              const float* __restrict__ W,
              const float* __restrict__ b,
              float* __restrict__ out,
              int idx_off)
{
    extern __shared__ float smem[];
    char*  sWt = reinterpret_cast<char*>(smem);          // 96 KB paired W
    float* sX  = smem + NUM_E * D_MODEL;                 // per-warp rings

    for (int d = threadIdx.x; d < D_MODEL; d += THREADS) {
        #pragma unroll
        for (int e = 0; e < NUM_E; ++e) {
            float v = W[e * D_MODEL + d];
            *reinterpret_cast<float*>(sWt + wt_off(d, e >> 2) + (e & 3) * 4) = v;
        }
    }
    __syncthreads();

    const int warp = threadIdx.x >> 5;
    const int lane = threadIdx.x & 31;
    const int o    = blockIdx.x + GRID * warp;   // oct id, per-SM balanced
    if (o >= NOCTS) return;

    float* ring = sX + warp * RING_FLOATS_PER_WARP;
    const unsigned ring_s =
        (unsigned)__cvta_generic_to_shared(ring) + lane * 16;
    const float4* __restrict__ ringv =
        reinterpret_cast<const float4*>(ring);

    const float* cur = x + (size_t)o * (TPW * D_MODEL) + lane * 4;

    #define ISSUE(c_, slot_)                                                  \
        do {                                                                  \
            const float* _s = cur + (c_) * CHUNK_D;                           \
            unsigned _d = ring_s + (slot_) * STAGE_BYTES;                     \
            _Pragma("unroll")                                                 \
            for (int _tt = 0; _tt < TPW; ++_tt)                               \
                asm volatile("cp.async.cg.shared.global [%0], [%1], 16;"      \
                             :: "r"(_d + _tt * (CHUNK_D * 4)),                \
                                "l"(_s + (size_t)_tt * D_MODEL) : "memory");  \
        } while (0)
    #define COMMIT() asm volatile("cp.async.commit_group;" ::: "memory")

    u64 acc[TPW][4];   // per token: (e0,e1),(e2,e3),(e4,e5),(e6,e7)
    #pragma unroll
    for (int t = 0; t < TPW; ++t)
        #pragma unroll
        for (int p = 0; p < 4; ++p)
            acc[t][p] = 0ull;

    ISSUE(0, 0); COMMIT();
    ISSUE(1, 1); COMMIT();

    #pragma unroll
    for (int c = 0; c < NCHUNK; ++c) {
        if (c < NCHUNK - 1)
            asm volatile("cp.async.wait_group 1;" ::: "memory");
        else
            asm volatile("cp.async.wait_group 0;" ::: "memory");

        const int slot = c & 1;
        const int dbase = c * CHUNK_D + lane * 4;

        // Pull this stage's x into registers (conflict-free LDS.128).
        float4 xv[TPW];
        #pragma unroll
        for (int tt = 0; tt < TPW; ++tt)
            xv[tt] = ringv[slot * (STAGE_BYTES / 16) + tt * (CHUNK_D / 4) + lane];

        // Refill the freed slot immediately (x already in regs).
        if (c < NCHUNK - 2) { ISSUE(c + 2, slot); COMMIT(); }

        #define KSTEP(k_, comp_)                                              \
            do {                                                              \
                const ulonglong2 w01 = *reinterpret_cast<const ulonglong2*>(  \
                    sWt + wt_off(dbase + (k_), 0));                           \
                const ulonglong2 w45 = *reinterpret_cast<const ulonglong2*>(  \
                    sWt + wt_off(dbase + (k_), 1));                           \
                _Pragma("unroll")                                             \
                for (int _tt = 0; _tt < TPW; ++_tt) {                         \
                    const u64 a = dup2(xv[_tt].comp_);                        \
                    acc[_tt][0] = ffma2(a, w01.x, acc[_tt][0]);               \
                    acc[_tt][1] = ffma2(a, w01.y, acc[_tt][1]);               \
                    acc[_tt][2] = ffma2(a, w45.x, acc[_tt][2]);               \
                    acc[_tt][3] = ffma2(a, w45.y, acc[_tt][3]);               \
                }                                                             \
            } while (0)

        KSTEP(0, x);
        KSTEP(1, y);
        KSTEP(2, z);
        KSTEP(3, w);
        #undef KSTEP
    }

    // ---- epilogue: butterfly reduce packed expert pairs ----
    #pragma unroll
    for (int off = 16; off > 0; off >>= 1)
        #pragma unroll
        for (int tt = 0; tt < TPW; ++tt)
            #pragma unroll
            for (int p = 0; p < 4; ++p)
                acc[tt][p] = addf2(acc[tt][p], shflx64(acc[tt][p], off));

    if (lane < TPW) {
        const int tok = o * TPW + lane;

        float logit[NUM_E];
        #pragma unroll
        for (int p = 0; p < 4; ++p) {
            logit[2 * p]     = __uint_as_float((unsigned)acc[lane][p])
                               + __ldg(&b[2 * p]);
            logit[2 * p + 1] = __uint_as_float((unsigned)(acc[lane][p] >> 32))
                               + __ldg(&b[2 * p + 1]);
        }

        float m = logit[0];
        #pragma unroll
        for (int e = 1; e < NUM_E; ++e) m = fmaxf(m, logit[e]);

        float ex[NUM_E], Z = 0.0f;
        #pragma unroll
        for (int e = 0; e < NUM_E; ++e) { ex[e] = __expf(logit[e] - m); Z += ex[e]; }
        const float invZ = 1.0f / Z;

        float sc[NUM_E];
        #pragma unroll
        for (int e = 0; e < NUM_E; ++e) sc[e] = ex[e] * invZ;

        int i1 = 0;
        #pragma unroll
        for (int e = 1; e < NUM_E; ++e) if (sc[e] > sc[i1]) i1 = e;
        int i2 = (i1 == 0) ? 1 : 0;
        #pragma unroll
        for (int e = 0; e < NUM_E; ++e)
            if (e != i1 && sc[e] > sc[i2]) i2 = e;

        const float v1 = sc[i1];
        const float v2 = sc[i2];
        const float e2 = __expf(v2 - v1);
        const float r1 = 1.0f / (1.0f + e2);
        const float r2 = 1.0f - r1;

        out[(size_t)tok * 2 + 0] = r1;
        out[(size_t)tok * 2 + 1] = r2;
        out[(size_t)idx_off + (size_t)tok * 2 + 0] = (float)i1;
        out[(size_t)idx_off + (size_t)tok * 2 + 1] = (float)i2;
    }
    #undef ISSUE
    #undef COMMIT
}

extern "C" void kernel_launch(void* const* d_in, const int* in_sizes, int n_in,
                              void* d_out, int out_size)
{
    const float* x = (const float*)d_in[0];
    const float* W = (const float*)d_in[1];
    const float* b = (const float*)d_in[2];
    float* out = (float*)d_out;

    const int idx_off = out_size / 2;

    cudaFuncSetAttribute(gating_kernel,
                         cudaFuncAttributeMaxDynamicSharedMemorySize,
                         (int)SMEM_BYTES);

    gating_kernel<<<GRID, THREADS, SMEM_BYTES>>>(x, W, b, out, idx_off);
}

// round 13
// speedup vs baseline: 1.2233x; 1.2233x over previous
#include <cuda_runtime.h>
#include <math.h>

#define D_MODEL   3072
#define NUM_E     8
#define N_TOKENS  16384
#define TPW       4                        // tokens per warp-quad
#define WARPS_PB  16
#define THREADS   (WARPS_PB * 32)          // 512
#define SUPER_D   256                      // floats of D per super-stage
#define SUB_D     128                      // floats per compute sub-chunk
#define NSUP      (D_MODEL / SUPER_D)      // 12 super-stages per quad
#define GRID      148
#define NWARPS_G  (GRID * WARPS_PB)        // 2368
#define NQUADS    (N_TOKENS / TPW)         // 4096
#define ROW_V     (D_MODEL / 4)            // 768 16B elems per W row
#define SEG_BYTES   (SUPER_D * 4)          // 1024 B per token per super-stage
#define SSTAGE_BYTES (TPW * SEG_BYTES)     // 4096 B per super-stage
#define RING_BYTES_PER_WARP (2 * SSTAGE_BYTES)   // 8 KB (2 slots)
// smem: [mbar 16*2*8B = 256] [W 96 KB] [rings 128 KB] = 229,632 B
#define SMEM_MBAR_BYTES 256
#define SMEM_BYTES (SMEM_MBAR_BYTES + NUM_E * D_MODEL * 4 + WARPS_PB * RING_BYTES_PER_WARP)

typedef unsigned long long u64;

__device__ __forceinline__ u64 ffma2(u64 a, u64 b, u64 c) {
    u64 d;
    asm("fma.rn.f32x2 %0, %1, %2, %3;" : "=l"(d) : "l"(a), "l"(b), "l"(c));
    return d;
}
__device__ __forceinline__ float unpack_sum(u64 v) {
    return __uint_as_float((unsigned)(v & 0xFFFFFFFFull)) +
           __uint_as_float((unsigned)(v >> 32));
}

__global__ void __launch_bounds__(THREADS, 1)
gating_kernel(const float* __restrict__ x,
              const float* __restrict__ W,
              const float* __restrict__ b,
              float* __restrict__ out,
              int idx_off)
{
    extern __shared__ float smem[];
    u64*   mbar = reinterpret_cast<u64*>(smem);                 // [16][2]
    float* sW   = smem + SMEM_MBAR_BYTES / 4;                   // [8][3072]
    float* sX   = sW + NUM_E * D_MODEL;                         // rings

    const int warp = threadIdx.x >> 5;
    const int lane = threadIdx.x & 31;
    const int bid  = blockIdx.x;

    // Cooperative load of W (plain [e][d] layout, R9-proven).
    {
        const float4* Wv = reinterpret_cast<const float4*>(W);
        float4* sWv4 = reinterpret_cast<float4*>(sW);
        #pragma unroll 4
        for (int i = threadIdx.x; i < NUM_E * D_MODEL / 4; i += THREADS)
            sWv4[i] = Wv[i];
    }

    // Per-warp mbarriers (2 slots).
    const unsigned mbar_s =
        (unsigned)__cvta_generic_to_shared(&mbar[warp * 2]);
    if (lane == 0) {
        asm volatile("mbarrier.init.shared.b64 [%0], 1;" :: "r"(mbar_s) : "memory");
        asm volatile("mbarrier.init.shared.b64 [%0], 1;" :: "r"(mbar_s + 8) : "memory");
        asm volatile("fence.proxy.async.shared::cta;" ::: "memory");
    }
    __syncthreads();

    float* ring = sX + warp * (RING_BYTES_PER_WARP / 4);
    const unsigned ring_s = (unsigned)__cvta_generic_to_shared(ring);
    const ulonglong2* __restrict__ ringv =
        reinterpret_cast<const ulonglong2*>(ring);
    const ulonglong2* __restrict__ sWv =
        reinterpret_cast<const ulonglong2*>(sW);

    // Persistent schedule (R4/R9-proven).
    const int q0 = bid + GRID * warp;                 // < 2368
    const int nq = (q0 + NWARPS_G < NQUADS) ? 2 : 1;
    const int T  = nq * NSUP;                         // 12 or 24 super-stages

    // super-stage t -> quad j = t/12, seg s = t%12, slot t&1
    #define ISSUE_SUPER(t_)                                                    \
        do {                                                                   \
            if (lane == 0) {                                                   \
                int _t = (t_);                                                 \
                int _j = _t / NSUP;                                            \
                int _s = _t - _j * NSUP;                                       \
                const float* _src = x + (size_t)(q0 + _j * NWARPS_G)           \
                                        * (TPW * D_MODEL) + _s * SUPER_D;      \
                unsigned _mb  = mbar_s + (_t & 1) * 8;                         \
                unsigned _dst = ring_s + (_t & 1) * SSTAGE_BYTES;              \
                asm volatile(                                                  \
                    "mbarrier.arrive.expect_tx.shared.b64 _, [%0], %1;"        \
                    :: "r"(_mb), "r"(SSTAGE_BYTES) : "memory");                \
                _Pragma("unroll")                                              \
                for (int _tt = 0; _tt < TPW; ++_tt)                            \
                    asm volatile(                                              \
                        "cp.async.bulk.shared::cta.global"                     \
                        ".mbarrier::complete_tx::bytes [%0], [%1], %2, [%3];"  \
                        :: "r"(_dst + _tt * SEG_BYTES),                        \
                           "l"(_src + (size_t)_tt * D_MODEL),                  \
                           "r"(SEG_BYTES), "r"(_mb) : "memory");               \
            }                                                                  \
        } while (0)

    u64 acc[TPW][NUM_E];
    #pragma unroll
    for (int t = 0; t < TPW; ++t)
        #pragma unroll
        for (int e = 0; e < NUM_E; ++e)
            acc[t][e] = 0ull;

    ISSUE_SUPER(0);
    ISSUE_SUPER(1);

    for (int t = 0; t < T; ++t) {
        const int slot = t & 1;
        const unsigned phase = (unsigned)((t >> 1) & 1);

        // Wait for super-stage t (acquire orders TMA writes before our LDS).
        {
            const unsigned mb = mbar_s + slot * 8;
            unsigned done;
            asm volatile(
                "{\n\t.reg .pred p;\n\t"
                "mbarrier.try_wait.parity.acquire.cta.shared::cta.b64 p, [%1], %2;\n\t"
                "selp.b32 %0, 1, 0, p;\n\t}"
                : "=r"(done) : "r"(mb), "r"(phase) : "memory");
            while (!done) {
                asm volatile(
                    "{\n\t.reg .pred p;\n\t"
                    "mbarrier.try_wait.parity.acquire.cta.shared::cta.b64 p, [%1], %2, 0x989680;\n\t"
                    "selp.b32 %0, 1, 0, p;\n\t}"
                    : "=r"(done) : "r"(mb), "r"(phase) : "memory");
            }
        }

        const int j = t / NSUP;
        const int s = t - j * NSUP;

        // Two 128-d sub-chunks; R9-proven inner block each.
        #pragma unroll
        for (int c2 = 0; c2 < 2; ++c2) {
            const int cc = s * 2 + c2;   // chunk index within quad (0..23)

            // x: lane reads 16B of token tt's segment, contiguous 512B/LDS.
            ulonglong2 xv[TPW];
            #pragma unroll
            for (int tt = 0; tt < TPW; ++tt)
                xv[tt] = *reinterpret_cast<const ulonglong2*>(
                    reinterpret_cast<const char*>(ringv)
                    + slot * SSTAGE_BYTES + tt * SEG_BYTES
                    + c2 * (SUB_D * 4) + lane * 16);

            #pragma unroll
            for (int e = 0; e < NUM_E; ++e) {
                const ulonglong2 wv =
                    sWv[e * ROW_V + cc * (SUB_D / 4) + lane];
                #pragma unroll
                for (int tt = 0; tt < TPW; ++tt) {
                    acc[tt][e] = ffma2(xv[tt].x, wv.x, acc[tt][e]);
                    acc[tt][e] = ffma2(xv[tt].y, wv.y, acc[tt][e]);
                }
            }
        }

        // Slot fully consumed; refill with super-stage t+2.
        if (t + 2 < T) ISSUE_SUPER(t + 2);

        if (s == NSUP - 1) {
            // ---- epilogue for quad q0 + j*NWARPS_G ----
            const int tok0 = (q0 + j * NWARPS_G) * TPW;

            float red[TPW][NUM_E];
            #pragma unroll
            for (int tt = 0; tt < TPW; ++tt)
                #pragma unroll
                for (int e = 0; e < NUM_E; ++e) {
                    red[tt][e] = unpack_sum(acc[tt][e]);
                    acc[tt][e] = 0ull;
                }

            #pragma unroll
            for (int off = 16; off > 0; off >>= 1)
                #pragma unroll
                for (int tt = 0; tt < TPW; ++tt)
                    #pragma unroll
                    for (int e = 0; e < NUM_E; ++e)
                        red[tt][e] += __shfl_xor_sync(0xFFFFFFFFu, red[tt][e], off);

            if (lane < TPW) {
                const int tok = tok0 + lane;

                float logit[NUM_E];
                #pragma unroll
                for (int e = 0; e < NUM_E; ++e)
                    logit[e] = red[lane][e] + __ldg(&b[e]);

                float m = logit[0];
                #pragma unroll
                for (int e = 1; e < NUM_E; ++e) m = fmaxf(m, logit[e]);

                float ex[NUM_E], Z = 0.0f;
                #pragma unroll
                for (int e = 0; e < NUM_E; ++e) { ex[e] = __expf(logit[e] - m); Z += ex[e]; }
                const float invZ = 1.0f / Z;

                float sc[NUM_E];
                #pragma unroll
                for (int e = 0; e < NUM_E; ++e) sc[e] = ex[e] * invZ;

                int i1 = 0;
                #pragma unroll
                for (int e = 1; e < NUM_E; ++e) if (sc[e] > sc[i1]) i1 = e;
                int i2 = (i1 == 0) ? 1 : 0;
                #pragma unroll
                for (int e = 0; e < NUM_E; ++e)
                    if (e != i1 && sc[e] > sc[i2]) i2 = e;

                const float v1 = sc[i1];
                const float v2 = sc[i2];
                const float e2 = __expf(v2 - v1);
                const float r1 = 1.0f / (1.0f + e2);
                const float r2 = 1.0f - r1;

                out[(size_t)tok * 2 + 0] = r1;
                out[(size_t)tok * 2 + 1] = r2;
                out[(size_t)idx_off + (size_t)tok * 2 + 0] = (float)i1;
                out[(size_t)idx_off + (size_t)tok * 2 + 1] = (float)i2;
            }
        }
    }
    #undef ISSUE_SUPER
}

extern "C" void kernel_launch(void* const* d_in, const int* in_sizes, int n_in,
                              void* d_out, int out_size)
{
    const float* x = (const float*)d_in[0];
    const float* W = (const float*)d_in[1];
    const float* b = (const float*)d_in[2];
    float* out = (float*)d_out;

    const int idx_off = out_size / 2;

    cudaFuncSetAttribute(gating_kernel,
                         cudaFuncAttributeMaxDynamicSharedMemorySize,
                         (int)SMEM_BYTES);

    gating_kernel<<<GRID, THREADS, SMEM_BYTES>>>(x, W, b, out, idx_off);
}

// round 14
// speedup vs baseline: 1.2355x; 1.0099x over previous
#include <cuda_runtime.h>
#include <math.h>

#define D_MODEL   3072
#define NUM_E     8
#define N_TOKENS  16384
#define TPW       4                       // tokens per warp-quad
#define WARPS_PB  16
#define THREADS   (WARPS_PB * 32)         // 512
#define CHUNK_D   128                     // floats of D per pipeline stage
#define NCHUNK    (D_MODEL / CHUNK_D)     // 24 (divisible by NSTAGE=3)
#define NSTAGE    3                       // ring slots; 2 stages in flight (R4)
#define GRID      148
#define NWARPS_G  (GRID * WARPS_PB)       // 2368
#define NQUADS    (N_TOKENS / TPW)        // 4096
#define ROW_V     (D_MODEL / 4)           // 768 16B elems per W row
#define STAGE_BYTES (TPW * CHUNK_D * 4)   // 2048
#define RING_FLOATS_PER_WARP (NSTAGE * TPW * CHUNK_D)    // 1536 floats = 6 KB
#define SMEM_BYTES ((NUM_E * D_MODEL + WARPS_PB * RING_FLOATS_PER_WARP) * 4)  // 192 KB

typedef unsigned long long u64;

__device__ __forceinline__ u64 ffma2(u64 a, u64 b, u64 c) {
    u64 d;
    asm("fma.rn.f32x2 %0, %1, %2, %3;" : "=l"(d) : "l"(a), "l"(b), "l"(c));
    return d;
}
__device__ __forceinline__ float unpack_sum(u64 v) {
    return __uint_as_float((unsigned)(v & 0xFFFFFFFFull)) +
           __uint_as_float((unsigned)(v >> 32));
}

__global__ void __launch_bounds__(THREADS, 1)
gating_kernel(const float* __restrict__ x,
              const float* __restrict__ W,
              const float* __restrict__ b,
              float* __restrict__ out,
              int idx_off)
{
    extern __shared__ float smem[];
    float* sW = smem;                                   // [8][3072]
    float* sX = smem + NUM_E * D_MODEL;                 // per-warp rings

    {
        const float4* Wv = reinterpret_cast<const float4*>(W);
        float4* sWv4 = reinterpret_cast<float4*>(sW);
        #pragma unroll 4
        for (int i = threadIdx.x; i < NUM_E * D_MODEL / 4; i += THREADS)
            sWv4[i] = Wv[i];
    }

    const int warp = threadIdx.x >> 5;
    const int lane = threadIdx.x & 31;
    const int bid  = blockIdx.x;

    // Bias into registers before the mainloop.
    float bias[NUM_E];
    #pragma unroll
    for (int e = 0; e < NUM_E; ++e) bias[e] = __ldg(&b[e]);

    __syncthreads();

    float* ring = sX + warp * RING_FLOATS_PER_WARP;
    const unsigned ring_s =
        (unsigned)__cvta_generic_to_shared(ring) + lane * 16;
    const ulonglong2* __restrict__ ringv =
        reinterpret_cast<const ulonglong2*>(ring);
    const ulonglong2* __restrict__ sWv =
        reinterpret_cast<const ulonglong2*>(sW);

    // R4-proven persistent schedule: quads q0 and maybe q0 + 2368.
    const int q0 = bid + GRID * warp;                 // < 2368
    const int nq = (q0 + NWARPS_G < NQUADS) ? 2 : 1;

    const size_t QSTRIDE = (size_t)NWARPS_G * (TPW * D_MODEL);
    const float* cur = x + (size_t)q0 * (TPW * D_MODEL) + lane * 4;

    // All ring/W offsets compile-time static at expansion sites (24 % 3 == 0).
    #define ISSUE(base_, c_, slot_)                                           \
        do {                                                                  \
            const float* _s = (base_) + (c_) * CHUNK_D;                       \
            unsigned _d = ring_s + (slot_) * STAGE_BYTES;                     \
            _Pragma("unroll")                                                 \
            for (int _tt = 0; _tt < TPW; ++_tt)                               \
                asm volatile("cp.async.cg.shared.global [%0], [%1], 16;"      \
                             :: "r"(_d + _tt * (CHUNK_D * 4)),                \
                                "l"(_s + (size_t)_tt * D_MODEL) : "memory");  \
        } while (0)
    #define COMMIT() asm volatile("cp.async.commit_group;" ::: "memory")
    #define WAITG1() asm volatile("cp.async.wait_group 1;" ::: "memory")
    #define WAITG0() asm volatile("cp.async.wait_group 0;" ::: "memory")

    u64 acc[TPW][NUM_E];
    #pragma unroll
    for (int t = 0; t < TPW; ++t)
        #pragma unroll
        for (int e = 0; e < NUM_E; ++e)
            acc[t][e] = 0ull;

    // Prologue: 2 stages in flight (R4 schedule).
    ISSUE(cur, 0, 0); COMMIT();
    ISSUE(cur, 1, 1); COMMIT();

    for (int j = 0; j < nq; ++j) {
        const float* nxt = cur + QSTRIDE;
        const bool more = (j + 1 < nq);

        #pragma unroll
        for (int c = 0; c < NCHUNK; ++c) {
            // Stage (j,c) complete; at most 1 newer pending.
            if (c == NCHUNK - 1 && !more) WAITG0(); else WAITG1();

            // Keep 2 in flight: issue stage c+2 (this quad or next).
            if (c < NCHUNK - 2) {
                ISSUE(cur, c + 2, (c + 2) % NSTAGE);
                COMMIT();
            } else if (more) {
                ISSUE(nxt, c + 2 - NCHUNK, (c + 2) % NSTAGE);
                COMMIT();
            }

            // Compute stage (c, slot c%3): static smem offsets.
            const ulonglong2* xs = ringv + (c % NSTAGE) * (TPW * CHUNK_D / 4);
            ulonglong2 xv[TPW];
            #pragma unroll
            for (int tt = 0; tt < TPW; ++tt)
                xv[tt] = xs[tt * (CHUNK_D / 4) + lane];

            #pragma unroll
            for (int e = 0; e < NUM_E; ++e) {
                const ulonglong2 wv =
                    sWv[e * ROW_V + c * (CHUNK_D / 4) + lane];
                #pragma unroll
                for (int tt = 0; tt < TPW; ++tt) {
                    acc[tt][e] = ffma2(xv[tt].x, wv.x, acc[tt][e]);
                    acc[tt][e] = ffma2(xv[tt].y, wv.y, acc[tt][e]);
                }
            }
        }

        // ---- epilogue for quad q0 + j*NWARPS_G ----
        {
            const int tok0 = (q0 + j * NWARPS_G) * TPW;

            float red[TPW][NUM_E];
            #pragma unroll
            for (int tt = 0; tt < TPW; ++tt)
                #pragma unroll
                for (int e = 0; e < NUM_E; ++e) {
                    red[tt][e] = unpack_sum(acc[tt][e]);
                    acc[tt][e] = 0ull;
                }

            #pragma unroll
            for (int off = 16; off > 0; off >>= 1)
                #pragma unroll
                for (int tt = 0; tt < TPW; ++tt)
                    #pragma unroll
                    for (int e = 0; e < NUM_E; ++e)
                        red[tt][e] += __shfl_xor_sync(0xFFFFFFFFu, red[tt][e], off);

            if (lane < TPW) {
                const int tok = tok0 + lane;

                float logit[NUM_E];
                #pragma unroll
                for (int e = 0; e < NUM_E; ++e)
                    logit[e] = red[lane][e] + bias[e];

                float m = logit[0];
                #pragma unroll
                for (int e = 1; e < NUM_E; ++e) m = fmaxf(m, logit[e]);

                float ex[NUM_E], Z = 0.0f;
                #pragma unroll
                for (int e = 0; e < NUM_E; ++e) { ex[e] = __expf(logit[e] - m); Z += ex[e]; }
                const float invZ = 1.0f / Z;

                float sc[NUM_E];
                #pragma unroll
                for (int e = 0; e < NUM_E; ++e) sc[e] = ex[e] * invZ;

                int i1 = 0;
                #pragma unroll
                for (int e = 1; e < NUM_E; ++e) if (sc[e] > sc[i1]) i1 = e;
                int i2 = (i1 == 0) ? 1 : 0;
                #pragma unroll
                for (int e = 0; e < NUM_E; ++e)
                    if (e != i1 && sc[e] > sc[i2]) i2 = e;

                const float v1 = sc[i1];
                const float v2 = sc[i2];
                const float e2 = __expf(v2 - v1);
                const float r1 = 1.0f / (1.0f + e2);
                const float r2 = 1.0f - r1;

                out[(size_t)tok * 2 + 0] = r1;
                out[(size_t)tok * 2 + 1] = r2;
                out[(size_t)idx_off + (size_t)tok * 2 + 0] = (float)i1;
                out[(size_t)idx_off + (size_t)tok * 2 + 1] = (float)i2;
            }
        }

        cur = nxt;
    }
    #undef ISSUE
    #undef COMMIT
    #undef WAITG1
    #undef WAITG0
}

extern "C" void kernel_launch(void* const* d_in, const int* in_sizes, int n_in,
                              void* d_out, int out_size)
{
    const float* x = (const float*)d_in[0];
    const float* W = (const float*)d_in[1];
    const float* b = (const float*)d_in[2];
    float* out = (float*)d_out;

    const int idx_off = out_size / 2;

    cudaFuncSetAttribute(gating_kernel,
                         cudaFuncAttributeMaxDynamicSharedMemorySize,
                         (int)SMEM_BYTES);

    gating_kernel<<<GRID, THREADS, SMEM_BYTES>>>(x, W, b, out, idx_off);
}

// round 15
// speedup vs baseline: 1.2961x; 1.0491x over previous
#include <cuda_runtime.h>
#include <math.h>

#define D_MODEL   3072
#define NUM_E     8
#define N_TOKENS  16384
#define TPW       4                       // tokens per warp-quad
#define WARPS_PB  16
#define THREADS   (WARPS_PB * 32)         // 512
#define CHUNK_D   128                     // floats of D per stage
#define NCHUNK    (D_MODEL / CHUNK_D)     // 24 (divisible by PF=3)
#define PF        3                       // register prefetch depth
#define GRID      148
#define NWARPS_G  (GRID * WARPS_PB)       // 2368
#define NQUADS    (N_TOKENS / TPW)        // 4096
#define ROW_F4    (D_MODEL / 4)           // 768 float4 per token row
#define SMEM_BYTES (NUM_E * D_MODEL * 4)  // 96 KB paired-transposed W

typedef unsigned long long u64;

__device__ __forceinline__ u64 ffma2(u64 a, u64 b, u64 c) {
    u64 d;
    asm("fma.rn.f32x2 %0, %1, %2, %3;" : "=l"(d) : "l"(a), "l"(b), "l"(c));
    return d;
}
__device__ __forceinline__ u64 addf2(u64 a, u64 b) {
    u64 d;
    asm("add.rn.f32x2 %0, %1, %2;" : "=l"(d) : "l"(a), "l"(b));
    return d;
}
__device__ __forceinline__ u64 dup2(float f) {
    u64 r; unsigned u = __float_as_uint(f);
    asm("mov.b64 %0, {%1, %1};" : "=l"(r) : "r"(u));
    return r;
}
__device__ __forceinline__ u64 shflx64(u64 v, int m) {
    unsigned lo = (unsigned)v, hi = (unsigned)(v >> 32);
    lo = __shfl_xor_sync(0xFFFFFFFFu, lo, m);
    hi = __shfl_xor_sync(0xFFFFFFFFu, hi, m);
    return ((u64)hi << 32) | lo;
}
// Paired-transposed W (R10-verified numerics): row d holds e0..e7 (32 B);
// 16B-granule XOR swizzle -> conflict-free LDS.128.
__device__ __forceinline__ unsigned wt_off(int d, int h) {
    unsigned o = (unsigned)d * 32u + (unsigned)h * 16u;
    return o ^ ((((unsigned)d >> 2) & 7u) << 4);
}

__global__ void __launch_bounds__(THREADS, 1)
gating_kernel(const float* __restrict__ x,
              const float* __restrict__ W,
              const float* __restrict__ b,
              float* __restrict__ out,
              int idx_off)
{
    extern __shared__ char sWt[];   // 96 KB paired W

    for (int d = threadIdx.x; d < D_MODEL; d += THREADS) {
        #pragma unroll
        for (int e = 0; e < NUM_E; ++e) {
            float v = W[e * D_MODEL + d];
            *reinterpret_cast<float*>(sWt + wt_off(d, e >> 2) + (e & 3) * 4) = v;
        }
    }
    __syncthreads();

    const int warp = threadIdx.x >> 5;
    const int lane = threadIdx.x & 31;
    const int bid  = blockIdx.x;

    // R4-proven persistent schedule: quads q0 and maybe q0 + 2368.
    const int q0 = bid + GRID * warp;                 // < 2368
    const int nq = (q0 + NWARPS_G < NQUADS) ? 2 : 1;

    const size_t QSTRIDE = (size_t)NWARPS_G * (TPW * D_MODEL);
    const float4* cur =
        reinterpret_cast<const float4*>(x + (size_t)q0 * (TPW * D_MODEL)) + lane;

    float4 xpf[PF][TPW];   // 48 regs: 3-deep register prefetch

    #define ISSUE(base_, c_, slot_)                                           \
        do {                                                                  \
            const float4* _s = (base_) + (c_) * (CHUNK_D / 4);                \
            _Pragma("unroll")                                                 \
            for (int _tt = 0; _tt < TPW; ++_tt)                               \
                xpf[(slot_)][_tt] = __ldcs(_s + _tt * ROW_F4);                \
        } while (0)

    u64 acc[TPW][4];   // per token: (e0,e1),(e2,e3),(e4,e5),(e6,e7)
    #pragma unroll
    for (int t = 0; t < TPW; ++t)
        #pragma unroll
        for (int p = 0; p < 4; ++p)
            acc[t][p] = 0ull;

    // Prologue: 3 stages of x in flight (pure register scoreboard).
    ISSUE(cur, 0, 0);
    ISSUE(cur, 1, 1);
    ISSUE(cur, 2, 2);

    for (int j = 0; j < nq; ++j) {
        const float4* nxt = cur + QSTRIDE / 4;
        const bool more = (j + 1 < nq);

        #pragma unroll
        for (int c = 0; c < NCHUNK; ++c) {
            const int slot = c % PF;              // static: 24 % 3 == 0
            const int dbase = c * CHUNK_D + lane * 4;

            // One K-step per float4 component.
            #define KSTEP(k_, comp_)                                           \
                do {                                                           \
                    const ulonglong2 w01 =                                     \
                        *reinterpret_cast<const ulonglong2*>(                  \
                            sWt + wt_off(dbase + (k_), 0));                    \
                    const ulonglong2 w45 =                                     \
                        *reinterpret_cast<const ulonglong2*>(                  \
                            sWt + wt_off(dbase + (k_), 1));                    \
                    _Pragma("unroll")                                          \
                    for (int _tt = 0; _tt < TPW; ++_tt) {                      \
                        const u64 a = dup2(xpf[slot][_tt].comp_);              \
                        acc[_tt][0] = ffma2(a, w01.x, acc[_tt][0]);            \
                        acc[_tt][1] = ffma2(a, w01.y, acc[_tt][1]);            \
                        acc[_tt][2] = ffma2(a, w45.x, acc[_tt][2]);            \
                        acc[_tt][3] = ffma2(a, w45.y, acc[_tt][3]);            \
                    }                                                          \
                } while (0)

            KSTEP(0, x);
            KSTEP(1, y);
            KSTEP(2, z);
            KSTEP(3, w);
            #undef KSTEP

            // Refill the just-consumed slot with stage c+3.
            if (c < NCHUNK - PF) {
                ISSUE(cur, c + PF, slot);
            } else if (more) {
                ISSUE(nxt, c + PF - NCHUNK, slot);
            }
        }

        // ---- epilogue for quad q0 + j*NWARPS_G ----
        {
            const int tok0 = (q0 + j * NWARPS_G) * TPW;

            #pragma unroll
            for (int off = 16; off > 0; off >>= 1)
                #pragma unroll
                for (int tt = 0; tt < TPW; ++tt)
                    #pragma unroll
                    for (int p = 0; p < 4; ++p)
                        acc[tt][p] = addf2(acc[tt][p], shflx64(acc[tt][p], off));

            if (lane < TPW) {
                const int tok = tok0 + lane;

                float logit[NUM_E];
                #pragma unroll
                for (int p = 0; p < 4; ++p) {
                    logit[2 * p]     = __uint_as_float((unsigned)acc[lane][p])
                                       + __ldg(&b[2 * p]);
                    logit[2 * p + 1] = __uint_as_float((unsigned)(acc[lane][p] >> 32))
                                       + __ldg(&b[2 * p + 1]);
                }

                float m = logit[0];
                #pragma unroll
                for (int e = 1; e < NUM_E; ++e) m = fmaxf(m, logit[e]);

                float ex[NUM_E], Z = 0.0f;
                #pragma unroll
                for (int e = 0; e < NUM_E; ++e) { ex[e] = __expf(logit[e] - m); Z += ex[e]; }
                const float invZ = 1.0f / Z;

                float sc[NUM_E];
                #pragma unroll
                for (int e = 0; e < NUM_E; ++e) sc[e] = ex[e] * invZ;

                int i1 = 0;
                #pragma unroll
                for (int e = 1; e < NUM_E; ++e) if (sc[e] > sc[i1]) i1 = e;
                int i2 = (i1 == 0) ? 1 : 0;
                #pragma unroll
                for (int e = 0; e < NUM_E; ++e)
                    if (e != i1 && sc[e] > sc[i2]) i2 = e;

                const float v1 = sc[i1];
                const float v2 = sc[i2];
                const float e2 = __expf(v2 - v1);
                const float r1 = 1.0f / (1.0f + e2);
                const float r2 = 1.0f - r1;

                out[(size_t)tok * 2 + 0] = r1;
                out[(size_t)tok * 2 + 1] = r2;
                out[(size_t)idx_off + (size_t)tok * 2 + 0] = (float)i1;
                out[(size_t)idx_off + (size_t)tok * 2 + 1] = (float)i2;
            }

            // Reset accumulators for the next quad.
            #pragma unroll
            for (int tt = 0; tt < TPW; ++tt)
                #pragma unroll
                for (int p = 0; p < 4; ++p)
                    acc[tt][p] = 0ull;
        }

        cur = nxt;
    }
    #undef ISSUE
}

extern "C" void kernel_launch(void* const* d_in, const int* in_sizes, int n_in,
                              void* d_out, int out_size)
{
    const float* x = (const float*)d_in[0];
    const float* W = (const float*)d_in[1];
    const float* b = (const float*)d_in[2];
    float* out = (float*)d_out;

    const int idx_off = out_size / 2;

    cudaFuncSetAttribute(gating_kernel,
                         cudaFuncAttributeMaxDynamicSharedMemorySize,
                         (int)SMEM_BYTES);

    gating_kernel<<<GRID, THREADS, SMEM_BYTES>>>(x, W, b, out, idx_off);
}